// round 15
// baseline (speedup 1.0000x reference)
#include <cuda_runtime.h>
#include <cuda_bf16.h>
#include <cstdint>
#include <cstddef>

// Problem constants
#define V_SZ   100000
#define D_SZ   256
#define S_SZ   128
#define H_SZ   512
#define B_SZ   8192
#define K_SZ   32
#define NREG   60000
#define RARE   40000

// Work-queue tiling (conv tiles at the tail)
#define NB_C   313
#define NB_T   64
#define NB_MLP (NB_C + NB_T)       // 377
#define NCONV  160                 // 60000 = 160*375
#define NT_TOTAL (NB_MLP + NCONV)  // 537
#define GRID_W 148
#define NTHREADS 512               // 16 warps = 4/SMSP

// ---------------------------------------------------------------------------
// Scratch (device globals; allocation is forbidden)
// ---------------------------------------------------------------------------
__device__ __nv_bfloat16 g_cw1t[H_SZ * S_SZ];
__device__ __nv_bfloat16 g_cw2t[D_SZ * H_SZ];
__device__ __nv_bfloat16 g_tw1t[H_SZ * S_SZ];
__device__ __nv_bfloat16 g_tw2t[D_SZ * H_SZ];
__device__ __nv_bfloat16 g_v[V_SZ * D_SZ];      // unified V table (bf16)
__device__ __nv_bfloat16 g_tu[B_SZ * D_SZ];     // t-MLP rows (bf16)
__device__ float g_partial[B_SZ / 8];
__device__ unsigned g_ticket;
__device__ int g_tile;                          // queue head (reset by prep)

// ---------------------------------------------------------------------------
// Helpers
// ---------------------------------------------------------------------------
__device__ __forceinline__ uint32_t smem_u32(const void* p) {
    uint32_t a;
    asm("{ .reg .u64 t; cvta.to.shared.u64 t, %1; cvt.u32.u64 %0, t; }" : "=r"(a) : "l"(p));
    return a;
}
__device__ __forceinline__ void ldsm4(uint32_t& r0, uint32_t& r1, uint32_t& r2, uint32_t& r3,
                                      uint32_t addr) {
    asm volatile("ldmatrix.sync.aligned.m8n8.x4.shared.b16 {%0,%1,%2,%3}, [%4];"
                 : "=r"(r0), "=r"(r1), "=r"(r2), "=r"(r3) : "r"(addr));
}
__device__ __forceinline__ void mma16816(float* c, const uint32_t* a, const uint32_t* b) {
    asm volatile(
        "mma.sync.aligned.m16n8k16.row.col.f32.bf16.bf16.f32 "
        "{%0,%1,%2,%3}, {%4,%5,%6,%7}, {%8,%9}, {%0,%1,%2,%3};"
        : "+f"(c[0]), "+f"(c[1]), "+f"(c[2]), "+f"(c[3])
        : "r"(a[0]), "r"(a[1]), "r"(a[2]), "r"(a[3]), "r"(b[0]), "r"(b[1]));
}
#define CPA16(dst, src) \
    asm volatile("cp.async.cg.shared.global [%0], [%1], 16;" :: "r"(dst), "l"(src))
#define CPA_COMMIT() asm volatile("cp.async.commit_group;" ::: "memory")
#define CPA_WAIT0()  asm volatile("cp.async.wait_group 0;" ::: "memory")

// SMEM layout (bytes, dynamic)
#define SM_A    0
#define SM_W0   32768
#define SM_W1   65536
#define SM_H    98304
#define SM_TID  229376
#define SM_TID2 229384
#define SM_TOTAL 229392

// ---------------------------------------------------------------------------
// Persistent work kernel, 512 threads (4M x 4N warps, 32x32 per warp).
// Next-tile A-gather and W-chunk0 prime are overlapped with layer-2 compute:
//   c==4: thread0 pops next tile id; c==5: gather next A into SM_A (dead
//   after chunk 3); c==11: prime next W1-chunk0 into W0 (dead during c==11).
// ---------------------------------------------------------------------------
__global__ __launch_bounds__(NTHREADS) void work_kernel(
    const float* __restrict__ stoich, const int* __restrict__ pos_u,
    const float* __restrict__ v_emb,
    const float* __restrict__ cB1, const float* __restrict__ cB2,
    const float* __restrict__ tB1, const float* __restrict__ tB2)
{
    extern __shared__ char smem[];
    const uint32_t sb = smem_u32(smem);
    const int tid = threadIdx.x;
    const int lane = tid & 31;
    const int wid = tid >> 5;
    const int mw = wid & 3;
    const int nw = wid >> 2;

    // ---- gather helper (A rows of tile t into SM_A) ----
    auto gatherA = [&](int t) {
        const bool isC = t < NB_C;
        const int M  = isC ? RARE : B_SZ;
        const int m0 = (isC ? t : t - NB_C) * 128;
        #pragma unroll
        for (int i = 0; i < 8; i++) {
            int idx = i * NTHREADS + tid;
            int row = idx >> 5, c4 = idx & 31;
            int rl = m0 + row; if (rl > M - 1) rl = M - 1;
            int rg = isC ? (NREG + rl) : pos_u[rl];
            float4 f = ((const float4*)stoich)[(size_t)rg * 32 + c4];
            __nv_bfloat162 p0 = __float22bfloat162_rn(make_float2(f.x, f.y));
            __nv_bfloat162 p1 = __float22bfloat162_rn(make_float2(f.z, f.w));
            uint2 u; u.x = *(unsigned*)&p0; u.y = *(unsigned*)&p1;
            int ch = c4 >> 1;
            *(uint2*)(smem + SM_A + row * 256 + ((ch ^ (row & 7)) << 4) + (c4 & 1) * 8) = u;
        }
    };
    auto primeW0 = [&](int t) {   // issue W1-chunk0 of tile t into W0 + commit
        const __nv_bfloat16* W1t = (t < NB_C) ? g_cw1t : g_tw1t;
        #pragma unroll
        for (int i = 0; i < 4; i++) {
            int c = i * NTHREADS + tid;
            int r = c >> 4, ch = c & 15;
            CPA16(sb + SM_W0 + r * 256 + ((ch ^ (r & 7)) << 4),
                  (const uint4*)W1t + (size_t)r * 16 + ch);
        }
        CPA_COMMIT();
    };

    // ---- pop first tile ----
    if (tid == 0) *(int*)(smem + SM_TID) = atomicAdd(&g_tile, 1);
    __syncthreads();
    int t = *(int*)(smem + SM_TID);
    __syncthreads();
    bool primed = false;   // A gathered + W chunk0 committed for tile t?

    while (t < NT_TOTAL) {
        // ================= conversion tile =================
        if (t >= NB_MLP) {
            const int j = t - NB_MLP;
            const float4* src = (const float4*)v_emb + (size_t)j * 12000;
            uint2* dst = (uint2*)g_v + (size_t)j * 12000;
            #pragma unroll 4
            for (int i = tid; i < 12000; i += NTHREADS) {
                float4 f = src[i];
                __nv_bfloat162 p0 = __float22bfloat162_rn(make_float2(f.x, f.y));
                __nv_bfloat162 p1 = __float22bfloat162_rn(make_float2(f.z, f.w));
                uint2 u; u.x = *(unsigned*)&p0; u.y = *(unsigned*)&p1;
                dst[i] = u;
            }
            if (tid == 0) *(int*)(smem + SM_TID) = atomicAdd(&g_tile, 1);
            __syncthreads();
            t = *(int*)(smem + SM_TID);
            __syncthreads();
            primed = false;
            continue;
        }

        // ================= MLP tile =================
        const bool isC = t < NB_C;
        const __nv_bfloat16* W1t = isC ? g_cw1t : g_tw1t;
        const __nv_bfloat16* W2t = isC ? g_cw2t : g_tw2t;
        const float* b1 = isC ? cB1 : tB1;
        const float* b2 = isC ? cB2 : tB2;
        __nv_bfloat16* C = isC ? (g_v + (size_t)NREG * D_SZ) : g_tu;
        const int M  = isC ? RARE : B_SZ;
        const int m0 = (isC ? t : t - NB_C) * 128;

        if (!primed) {            // serial prologue (first tile / after conv)
            primeW0(t);
            gatherA(t);
        }

        float acc[2][4][4];
        int t_next = NT_TOTAL;    // set at c==5

        for (int c = 0; c < 12; c++) {
            CPA_WAIT0();
            __syncthreads();

            if (c == 4 && tid == 0)
                *(int*)(smem + SM_TID2) = atomicAdd(&g_tile, 1);   // visible at c==5

            if (c < 11) {
                int n = c + 1;
                uint32_t dst = sb + ((n & 1) ? SM_W1 : SM_W0);
                if (n < 4) {
                    #pragma unroll
                    for (int i = 0; i < 4; i++) {
                        int q = i * NTHREADS + tid;
                        int r = q >> 4, ch = q & 15;
                        CPA16(dst + r * 256 + ((ch ^ (r & 7)) << 4),
                              (const uint4*)W1t + (size_t)(n * 128 + r) * 16 + ch);
                    }
                } else {
                    int nc = (n - 4) >> 2, kc = (n - 4) & 3;
                    #pragma unroll
                    for (int i = 0; i < 4; i++) {
                        int q = i * NTHREADS + tid;
                        int r = q >> 4, ch = q & 15;
                        CPA16(dst + r * 256 + ((ch ^ (r & 7)) << 4),
                              (const uint4*)W2t + (size_t)(nc * 128 + r) * 64 + kc * 16 + ch);
                    }
                }
                CPA_COMMIT();
            }

            if (c == 5) {
                t_next = *(int*)(smem + SM_TID2);
                if (t_next < NB_MLP) gatherA(t_next);   // SM_A dead after chunk 3
            }
            if (c == 11 && t_next < NB_MLP)
                primeW0(t_next);                        // W0 dead during chunk 11

            const uint32_t wbase = sb + ((c & 1) ? SM_W1 : SM_W0);

            if (c < 4) {
                // ---------------- Layer 1 chunk c ----------------
                #pragma unroll
                for (int mt = 0; mt < 2; mt++)
                    #pragma unroll
                    for (int nt = 0; nt < 4; nt++)
                        #pragma unroll
                        for (int q = 0; q < 4; q++) acc[mt][nt][q] = 0.f;

                #pragma unroll
                for (int ks = 0; ks < 8; ks++) {
                    uint32_t a[2][4];
                    #pragma unroll
                    for (int mt = 0; mt < 2; mt++) {
                        int row = mw * 32 + mt * 16 + (lane & 15);
                        int ch  = ks * 2 + (lane >> 4);
                        ldsm4(a[mt][0], a[mt][1], a[mt][2], a[mt][3],
                              sb + SM_A + row * 256 + ((ch ^ (row & 7)) << 4));
                    }
                    uint32_t b[4][2];
                    #pragma unroll
                    for (int ntp = 0; ntp < 2; ntp++) {
                        int row = nw * 32 + ntp * 16 + (lane & 7) + ((lane >> 4) << 3);
                        int ch  = ks * 2 + ((lane >> 3) & 1);
                        ldsm4(b[2*ntp][0], b[2*ntp][1], b[2*ntp+1][0], b[2*ntp+1][1],
                              wbase + row * 256 + ((ch ^ (row & 7)) << 4));
                    }
                    #pragma unroll
                    for (int mt = 0; mt < 2; mt++)
                        #pragma unroll
                        for (int nt = 0; nt < 4; nt++)
                            mma16816(acc[mt][nt], a[mt], b[nt]);
                }

                // Epilogue: bias + relu -> bf16 hidden in SMEM
                #pragma unroll
                for (int mt = 0; mt < 2; mt++)
                    #pragma unroll
                    for (int nt = 0; nt < 4; nt++) {
                        int nloc = nw * 32 + nt * 8 + 2 * (lane & 3);
                        int ng = c * 128 + nloc;
                        float2 bb = *(const float2*)(b1 + ng);
                        float h0 = fmaxf(acc[mt][nt][0] + bb.x, 0.f);
                        float h1 = fmaxf(acc[mt][nt][1] + bb.y, 0.f);
                        float h2 = fmaxf(acc[mt][nt][2] + bb.x, 0.f);
                        float h3 = fmaxf(acc[mt][nt][3] + bb.y, 0.f);
                        __nv_bfloat162 p0 = __float22bfloat162_rn(make_float2(h0, h1));
                        __nv_bfloat162 p1 = __float22bfloat162_rn(make_float2(h2, h3));
                        int ch = ng >> 3, w = (ng & 7) * 2;
                        int r0 = mw * 32 + mt * 16 + (lane >> 2);
                        int r1 = r0 + 8;
                        *(unsigned*)(smem + SM_H + r0*1024 + ((ch ^ (r0 & 7)) << 4) + w) =
                            *(unsigned*)&p0;
                        *(unsigned*)(smem + SM_H + r1*1024 + ((ch ^ (r1 & 7)) << 4) + w) =
                            *(unsigned*)&p1;
                    }
            } else {
                // ---------------- Layer 2 chunk (nc, kc) ----------------
                const int nc = (c - 4) >> 2, kc = (c - 4) & 3;
                if (kc == 0) {
                    #pragma unroll
                    for (int mt = 0; mt < 2; mt++)
                        #pragma unroll
                        for (int nt = 0; nt < 4; nt++)
                            #pragma unroll
                            for (int q = 0; q < 4; q++) acc[mt][nt][q] = 0.f;
                }

                #pragma unroll
                for (int ks = 0; ks < 8; ks++) {
                    uint32_t a[2][4];
                    #pragma unroll
                    for (int mt = 0; mt < 2; mt++) {
                        int row = mw * 32 + mt * 16 + (lane & 15);
                        int ch  = kc * 16 + ks * 2 + (lane >> 4);
                        ldsm4(a[mt][0], a[mt][1], a[mt][2], a[mt][3],
                              sb + SM_H + row * 1024 + ((ch ^ (row & 7)) << 4));
                    }
                    uint32_t b[4][2];
                    #pragma unroll
                    for (int ntp = 0; ntp < 2; ntp++) {
                        int row = nw * 32 + ntp * 16 + (lane & 7) + ((lane >> 4) << 3);
                        int ch  = ks * 2 + ((lane >> 3) & 1);
                        ldsm4(b[2*ntp][0], b[2*ntp][1], b[2*ntp+1][0], b[2*ntp+1][1],
                              wbase + row * 256 + ((ch ^ (row & 7)) << 4));
                    }
                    #pragma unroll
                    for (int mt = 0; mt < 2; mt++)
                        #pragma unroll
                        for (int nt = 0; nt < 4; nt++)
                            mma16816(acc[mt][nt], a[mt], b[nt]);
                }

                if (kc == 3) {
                    #pragma unroll
                    for (int mt = 0; mt < 2; mt++)
                        #pragma unroll
                        for (int nt = 0; nt < 4; nt++) {
                            int ng = nc * 128 + nw * 32 + nt * 8 + 2 * (lane & 3);
                            float2 bb = *(const float2*)(b2 + ng);
                            int r0 = m0 + mw * 32 + mt * 16 + (lane >> 2);
                            int r1 = r0 + 8;
                            if (r0 < M) {
                                __nv_bfloat162 o = __float22bfloat162_rn(
                                    make_float2(acc[mt][nt][0] + bb.x, acc[mt][nt][1] + bb.y));
                                *(unsigned*)(C + (size_t)r0 * D_SZ + ng) = *(unsigned*)&o;
                            }
                            if (r1 < M) {
                                __nv_bfloat162 o = __float22bfloat162_rn(
                                    make_float2(acc[mt][nt][2] + bb.x, acc[mt][nt][3] + bb.y));
                                *(unsigned*)(C + (size_t)r1 * D_SZ + ng) = *(unsigned*)&o;
                            }
                        }
                }
            }
        }

        t = t_next;
        primed = (t_next < NB_MLP);   // A gathered + W0 committed already
    }
}

// ---------------------------------------------------------------------------
// Prep: reset queue + 4x coalesced weight transpose (fp32 -> bf16 K-major)
// ---------------------------------------------------------------------------
__global__ __launch_bounds__(256) void prep_kernel(
    const float* __restrict__ cw1, const float* __restrict__ cw2,
    const float* __restrict__ tw1, const float* __restrict__ tw2)
{
    const int bx = blockIdx.x;
    const int tid = threadIdx.x;
    if (bx == 0 && tid == 0) g_tile = 0;

    __shared__ float tile[32][33];
    const float* w; __nv_bfloat16* wt; int K, N, tt;
    if (bx < 64)       { w = cw1; wt = g_cw1t; K = S_SZ; N = H_SZ; tt = bx; }
    else if (bx < 128) { w = tw1; wt = g_tw1t; K = S_SZ; N = H_SZ; tt = bx - 64; }
    else if (bx < 256) { w = cw2; wt = g_cw2t; K = H_SZ; N = D_SZ; tt = bx - 128; }
    else               { w = tw2; wt = g_tw2t; K = H_SZ; N = D_SZ; tt = bx - 256; }

    const int Kt = K >> 5;
    const int kt = tt % Kt, nt = tt / Kt;
    const int cc = tid & 31, rr = tid >> 5;
    #pragma unroll
    for (int j = 0; j < 4; j++) {
        int row = rr + j * 8;
        tile[row][cc] = w[(size_t)(kt * 32 + row) * N + nt * 32 + cc];
    }
    __syncthreads();
    #pragma unroll
    for (int j = 0; j < 4; j++) {
        int row = rr + j * 8;
        wt[(size_t)(nt * 32 + row) * K + kt * 32 + cc] = __float2bfloat16(tile[cc][row]);
    }
}

// ---------------------------------------------------------------------------
// Scoring: one warp per pair, lane l owns cols [8l, 8l+8), bf16 g_v gathers.
// Fused final reduction via self-resetting ticket.
// ---------------------------------------------------------------------------
__device__ __forceinline__ float clip10(float x) { return fminf(fmaxf(x, -10.f), 10.f); }
__device__ __forceinline__ float warp_reduce(float v) {
    #pragma unroll
    for (int s = 16; s > 0; s >>= 1) v += __shfl_xor_sync(0xffffffffu, v, s);
    return v;
}
__device__ __forceinline__ float dot8_bf16(const float* eu, uint4 q) {
    unsigned uu[4] = {q.x, q.y, q.z, q.w};
    float dn = 0.f;
    #pragma unroll
    for (int j = 0; j < 4; j++) {
        __nv_bfloat162 h = *(__nv_bfloat162*)&uu[j];
        float2 f = __bfloat1622float2(h);
        dn += eu[2*j+0] * f.x + eu[2*j+1] * f.y;
    }
    return dn;
}

__global__ __launch_bounds__(256) void score_kernel(
    const int* __restrict__ pos_u, const int* __restrict__ pos_v,
    const int* __restrict__ neg_v,
    const float* __restrict__ u_emb, float* __restrict__ out)
{
    __shared__ float bsum[8];
    __shared__ int lastflag;
    const int warp = threadIdx.x >> 5;
    const int lane = threadIdx.x & 31;
    const int b = blockIdx.x * 8 + warp;

    const int pu = pos_u[b];
    const int pv = pos_v[b];

    float eu[8];
    if (pu < NREG) {
        const float4* p = (const float4*)(u_emb + (size_t)pu * D_SZ);
        float4 f0 = p[lane * 2 + 0];
        float4 f1 = p[lane * 2 + 1];
        eu[0]=f0.x; eu[1]=f0.y; eu[2]=f0.z; eu[3]=f0.w;
        eu[4]=f1.x; eu[5]=f1.y; eu[6]=f1.z; eu[7]=f1.w;
    } else {
        uint4 q = ((const uint4*)(g_tu + (size_t)b * D_SZ))[lane];
        unsigned uu[4] = {q.x, q.y, q.z, q.w};
        #pragma unroll
        for (int j = 0; j < 4; j++) {
            __nv_bfloat162 h = *(__nv_bfloat162*)&uu[j];
            float2 f = __bfloat1622float2(h);
            eu[2*j+0] = f.x; eu[2*j+1] = f.y;
        }
    }

    uint4 qv = ((const uint4*)(g_v + (size_t)pv * D_SZ))[lane];
    float d = warp_reduce(dot8_bf16(eu, qv));
    float x = clip10(d);
    float s = __logf(1.f + __expf(-fabsf(x))) - fminf(x, 0.f);

    const int mynv = neg_v[(size_t)b * K_SZ + lane];
    #pragma unroll 4
    for (int k = 0; k < K_SZ; k++) {
        int nv = __shfl_sync(0xffffffffu, mynv, k);
        uint4 qn = ((const uint4*)(g_v + (size_t)nv * D_SZ))[lane];
        float dn = warp_reduce(dot8_bf16(eu, qn));
        float xn = clip10(dn);
        s += fmaxf(xn, 0.f) + __logf(1.f + __expf(-fabsf(xn)));
    }

    if (lane == 0) bsum[warp] = 2.f * s;
    __syncthreads();
    if (threadIdx.x == 0) {
        float t = 0.f;
        #pragma unroll
        for (int i = 0; i < 8; i++) t += bsum[i];
        g_partial[blockIdx.x] = t;
        __threadfence();
        unsigned old = atomicInc(&g_ticket, gridDim.x - 1);
        lastflag = (old == gridDim.x - 1);
    }
    __syncthreads();

    if (lastflag) {
        __threadfence();
        __shared__ float red[256];
        float v = 0.f;
        #pragma unroll
        for (int j = 0; j < 4; j++)
            v += __ldcg(&g_partial[threadIdx.x * 4 + j]);
        red[threadIdx.x] = v;
        __syncthreads();
        #pragma unroll
        for (int st = 128; st > 0; st >>= 1) {
            if (threadIdx.x < st) red[threadIdx.x] += red[threadIdx.x + st];
            __syncthreads();
        }
        if (threadIdx.x == 0) out[0] = red[0] / (float)B_SZ;
    }
}

// ---------------------------------------------------------------------------
// Launch
// ---------------------------------------------------------------------------
extern "C" void kernel_launch(void* const* d_in, const int* in_sizes, int n_in,
                              void* d_out, int out_size)
{
    const int*   pos_u  = (const int*)  d_in[0];
    const int*   pos_v  = (const int*)  d_in[1];
    const int*   neg_v  = (const int*)  d_in[2];
    const float* u_emb  = (const float*)d_in[3];
    const float* v_emb  = (const float*)d_in[4];
    const float* stoich = (const float*)d_in[5];
    const float* tw1    = (const float*)d_in[6];
    const float* tb1    = (const float*)d_in[7];
    const float* tw2    = (const float*)d_in[8];
    const float* tb2    = (const float*)d_in[9];
    const float* cw1    = (const float*)d_in[10];
    const float* cb1    = (const float*)d_in[11];
    const float* cw2    = (const float*)d_in[12];
    const float* cb2    = (const float*)d_in[13];
    float* out = (float*)d_out;

    static bool attr_set = false;
    if (!attr_set) {
        cudaFuncSetAttribute(work_kernel, cudaFuncAttributeMaxDynamicSharedMemorySize,
                             SM_TOTAL);
        attr_set = true;
    }

    prep_kernel<<<384, 256>>>(cw1, cw2, tw1, tw2);
    work_kernel<<<GRID_W, NTHREADS, SM_TOTAL>>>(stoich, pos_u, v_emb, cb1, cb2, tb1, tb2);
    score_kernel<<<B_SZ / 8, 256>>>(pos_u, pos_v, neg_v, u_emb, out);

    (void)in_sizes; (void)n_in; (void)out_size;
}

// round 16
// speedup vs baseline: 1.0367x; 1.0367x over previous
#include <cuda_runtime.h>
#include <cuda_bf16.h>
#include <cstdint>
#include <cstddef>

// Problem constants
#define V_SZ   100000
#define D_SZ   256
#define S_SZ   128
#define H_SZ   512
#define B_SZ   8192
#define K_SZ   32
#define NREG   60000
#define RARE   40000

// Work-queue tiling (conv tiles at the tail)
#define NB_C   313                 // c-MLP tiles (ceil(40000/128))
#define NB_T   64                  // t-MLP tiles (8192/128)
#define NB_MLP (NB_C + NB_T)       // 377
#define NCONV  160                 // v_emb conversion chunks (60000 = 160*375)
#define NT_TOTAL (NB_MLP + NCONV)  // 537
#define GRID_W 148
#define NTHREADS 512               // 16 warps = 4/SMSP

// ---------------------------------------------------------------------------
// Scratch (device globals; allocation is forbidden)
// ---------------------------------------------------------------------------
__device__ __nv_bfloat16 g_cw1t[H_SZ * S_SZ];   // cw1^T [512x128] (K-major)
__device__ __nv_bfloat16 g_cw2t[D_SZ * H_SZ];   // cw2^T [256x512]
__device__ __nv_bfloat16 g_tw1t[H_SZ * S_SZ];   // tw1^T
__device__ __nv_bfloat16 g_tw2t[D_SZ * H_SZ];   // tw2^T
__device__ __nv_bfloat16 g_v[V_SZ * D_SZ];      // unified V table (bf16)
__device__ __nv_bfloat16 g_tu[B_SZ * D_SZ];     // t-MLP per pos_u row (bf16)
__device__ float g_partial[B_SZ / 8];           // 1024 block partials
__device__ unsigned g_ticket;                   // score reduction ticket (wraps)
__device__ int g_tile;                          // work-queue head (reset by prep)

// ---------------------------------------------------------------------------
// Helpers
// ---------------------------------------------------------------------------
__device__ __forceinline__ uint32_t smem_u32(const void* p) {
    uint32_t a;
    asm("{ .reg .u64 t; cvta.to.shared.u64 t, %1; cvt.u32.u64 %0, t; }" : "=r"(a) : "l"(p));
    return a;
}
__device__ __forceinline__ void ldsm4(uint32_t& r0, uint32_t& r1, uint32_t& r2, uint32_t& r3,
                                      uint32_t addr) {
    asm volatile("ldmatrix.sync.aligned.m8n8.x4.shared.b16 {%0,%1,%2,%3}, [%4];"
                 : "=r"(r0), "=r"(r1), "=r"(r2), "=r"(r3) : "r"(addr));
}
__device__ __forceinline__ void mma16816(float* c, const uint32_t* a, const uint32_t* b) {
    asm volatile(
        "mma.sync.aligned.m16n8k16.row.col.f32.bf16.bf16.f32 "
        "{%0,%1,%2,%3}, {%4,%5,%6,%7}, {%8,%9}, {%0,%1,%2,%3};"
        : "+f"(c[0]), "+f"(c[1]), "+f"(c[2]), "+f"(c[3])
        : "r"(a[0]), "r"(a[1]), "r"(a[2]), "r"(a[3]), "r"(b[0]), "r"(b[1]));
}
#define CPA16(dst, src) \
    asm volatile("cp.async.cg.shared.global [%0], [%1], 16;" :: "r"(dst), "l"(src))
#define CPA_COMMIT() asm volatile("cp.async.commit_group;" ::: "memory")
#define CPA_WAIT0()  asm volatile("cp.async.wait_group 0;" ::: "memory")

// SMEM layout (bytes, dynamic)
#define SM_A    0
#define SM_W0   32768
#define SM_W1   65536
#define SM_H    98304
#define SM_TID  229376
#define SM_TOTAL 229392

// ---------------------------------------------------------------------------
// Persistent work kernel (R13): 512 threads (4M x 4N warps, 32x32 per warp).
//  t in [0, 313): c-MLP tile  -> g_v rows [60000 + t*128 ...)
//  t in [313,377): t-MLP tile -> g_tu
//  t in [377,537): convert v_emb rows fp32 -> g_v bf16
// ---------------------------------------------------------------------------
__global__ __launch_bounds__(NTHREADS) void work_kernel(
    const float* __restrict__ stoich, const int* __restrict__ pos_u,
    const float* __restrict__ v_emb,
    const float* __restrict__ cB1, const float* __restrict__ cB2,
    const float* __restrict__ tB1, const float* __restrict__ tB2)
{
    extern __shared__ char smem[];
    const uint32_t sb = smem_u32(smem);
    const int tid = threadIdx.x;
    const int lane = tid & 31;
    const int wid = tid >> 5;       // 0..15
    const int mw = wid & 3;         // M-warp: 32-row stripe
    const int nw = wid >> 2;        // N-warp: 32-col stripe within 128-col chunk

    for (;;) {
        if (tid == 0) *(int*)(smem + SM_TID) = atomicAdd(&g_tile, 1);
        __syncthreads();
        const int t = *(int*)(smem + SM_TID);
        __syncthreads();
        if (t >= NT_TOTAL) break;

        // ---- conversion tile ----
        if (t >= NB_MLP) {
            const int j = t - NB_MLP;           // 375 rows -> 12000 float4
            const float4* src = (const float4*)v_emb + (size_t)j * 12000;
            uint2* dst = (uint2*)g_v + (size_t)j * 12000;
            #pragma unroll 4
            for (int i = tid; i < 12000; i += NTHREADS) {
                float4 f = src[i];
                __nv_bfloat162 p0 = __float22bfloat162_rn(make_float2(f.x, f.y));
                __nv_bfloat162 p1 = __float22bfloat162_rn(make_float2(f.z, f.w));
                uint2 u; u.x = *(unsigned*)&p0; u.y = *(unsigned*)&p1;
                dst[i] = u;
            }
            continue;
        }

        // ---- MLP tile ----
        const bool isC = t < NB_C;
        const __nv_bfloat16* W1t = isC ? g_cw1t : g_tw1t;
        const __nv_bfloat16* W2t = isC ? g_cw2t : g_tw2t;
        const float* b1 = isC ? cB1 : tB1;
        const float* b2 = isC ? cB2 : tB2;
        __nv_bfloat16* C = isC ? (g_v + (size_t)NREG * D_SZ) : g_tu;
        const int M  = isC ? RARE : B_SZ;
        const int m0 = (isC ? t : t - NB_C) * 128;

        // Prologue: async-load W chunk 0 (2048 uint4 over 512 threads)
        #pragma unroll
        for (int i = 0; i < 4; i++) {
            int c = i * NTHREADS + tid;
            int r = c >> 4, ch = c & 15;
            CPA16(sb + SM_W0 + r * 256 + ((ch ^ (r & 7)) << 4),
                  (const uint4*)W1t + (size_t)r * 16 + ch);
        }
        CPA_COMMIT();

        // Gather A rows from fp32 stoich -> bf16 swizzled SMEM (4096 float4)
        #pragma unroll
        for (int i = 0; i < 8; i++) {
            int idx = i * NTHREADS + tid;
            int row = idx >> 5, c4 = idx & 31;
            int rl = m0 + row; if (rl > M - 1) rl = M - 1;
            int rg = isC ? (NREG + rl) : pos_u[rl];
            float4 f = ((const float4*)stoich)[(size_t)rg * 32 + c4];
            __nv_bfloat162 p0 = __float22bfloat162_rn(make_float2(f.x, f.y));
            __nv_bfloat162 p1 = __float22bfloat162_rn(make_float2(f.z, f.w));
            uint2 u; u.x = *(unsigned*)&p0; u.y = *(unsigned*)&p1;
            int ch = c4 >> 1;
            *(uint2*)(smem + SM_A + row * 256 + ((ch ^ (row & 7)) << 4) + (c4 & 1) * 8) = u;
        }

        float acc[2][4][4];

        for (int c = 0; c < 12; c++) {
            CPA_WAIT0();
            __syncthreads();

            if (c < 11) {
                int n = c + 1;
                uint32_t dst = sb + ((n & 1) ? SM_W1 : SM_W0);
                if (n < 4) {
                    #pragma unroll
                    for (int i = 0; i < 4; i++) {
                        int q = i * NTHREADS + tid;
                        int r = q >> 4, ch = q & 15;
                        CPA16(dst + r * 256 + ((ch ^ (r & 7)) << 4),
                              (const uint4*)W1t + (size_t)(n * 128 + r) * 16 + ch);
                    }
                } else {
                    int nc = (n - 4) >> 2, kc = (n - 4) & 3;
                    #pragma unroll
                    for (int i = 0; i < 4; i++) {
                        int q = i * NTHREADS + tid;
                        int r = q >> 4, ch = q & 15;
                        CPA16(dst + r * 256 + ((ch ^ (r & 7)) << 4),
                              (const uint4*)W2t + (size_t)(nc * 128 + r) * 64 + kc * 16 + ch);
                    }
                }
                CPA_COMMIT();
            }

            const uint32_t wbase = sb + ((c & 1) ? SM_W1 : SM_W0);

            if (c < 4) {
                // ================= Layer 1 chunk c =================
                #pragma unroll
                for (int mt = 0; mt < 2; mt++)
                    #pragma unroll
                    for (int nt = 0; nt < 4; nt++)
                        #pragma unroll
                        for (int q = 0; q < 4; q++) acc[mt][nt][q] = 0.f;

                #pragma unroll
                for (int ks = 0; ks < 8; ks++) {
                    uint32_t a[2][4];
                    #pragma unroll
                    for (int mt = 0; mt < 2; mt++) {
                        int row = mw * 32 + mt * 16 + (lane & 15);
                        int ch  = ks * 2 + (lane >> 4);
                        ldsm4(a[mt][0], a[mt][1], a[mt][2], a[mt][3],
                              sb + SM_A + row * 256 + ((ch ^ (row & 7)) << 4));
                    }
                    uint32_t b[4][2];
                    #pragma unroll
                    for (int ntp = 0; ntp < 2; ntp++) {
                        int row = nw * 32 + ntp * 16 + (lane & 7) + ((lane >> 4) << 3);
                        int ch  = ks * 2 + ((lane >> 3) & 1);
                        ldsm4(b[2*ntp][0], b[2*ntp][1], b[2*ntp+1][0], b[2*ntp+1][1],
                              wbase + row * 256 + ((ch ^ (row & 7)) << 4));
                    }
                    #pragma unroll
                    for (int mt = 0; mt < 2; mt++)
                        #pragma unroll
                        for (int nt = 0; nt < 4; nt++)
                            mma16816(acc[mt][nt], a[mt], b[nt]);
                }

                // Epilogue: bias + relu -> bf16 hidden in SMEM
                #pragma unroll
                for (int mt = 0; mt < 2; mt++)
                    #pragma unroll
                    for (int nt = 0; nt < 4; nt++) {
                        int nloc = nw * 32 + nt * 8 + 2 * (lane & 3);
                        int ng = c * 128 + nloc;
                        float2 bb = *(const float2*)(b1 + ng);
                        float h0 = fmaxf(acc[mt][nt][0] + bb.x, 0.f);
                        float h1 = fmaxf(acc[mt][nt][1] + bb.y, 0.f);
                        float h2 = fmaxf(acc[mt][nt][2] + bb.x, 0.f);
                        float h3 = fmaxf(acc[mt][nt][3] + bb.y, 0.f);
                        __nv_bfloat162 p0 = __float22bfloat162_rn(make_float2(h0, h1));
                        __nv_bfloat162 p1 = __float22bfloat162_rn(make_float2(h2, h3));
                        int ch = ng >> 3, w = (ng & 7) * 2;
                        int r0 = mw * 32 + mt * 16 + (lane >> 2);
                        int r1 = r0 + 8;
                        *(unsigned*)(smem + SM_H + r0*1024 + ((ch ^ (r0 & 7)) << 4) + w) =
                            *(unsigned*)&p0;
                        *(unsigned*)(smem + SM_H + r1*1024 + ((ch ^ (r1 & 7)) << 4) + w) =
                            *(unsigned*)&p1;
                    }
            } else {
                // ================= Layer 2 chunk (nc, kc) =================
                const int nc = (c - 4) >> 2, kc = (c - 4) & 3;
                if (kc == 0) {
                    #pragma unroll
                    for (int mt = 0; mt < 2; mt++)
                        #pragma unroll
                        for (int nt = 0; nt < 4; nt++)
                            #pragma unroll
                            for (int q = 0; q < 4; q++) acc[mt][nt][q] = 0.f;
                }

                #pragma unroll
                for (int ks = 0; ks < 8; ks++) {
                    uint32_t a[2][4];
                    #pragma unroll
                    for (int mt = 0; mt < 2; mt++) {
                        int row = mw * 32 + mt * 16 + (lane & 15);
                        int ch  = kc * 16 + ks * 2 + (lane >> 4);
                        ldsm4(a[mt][0], a[mt][1], a[mt][2], a[mt][3],
                              sb + SM_H + row * 1024 + ((ch ^ (row & 7)) << 4));
                    }
                    uint32_t b[4][2];
                    #pragma unroll
                    for (int ntp = 0; ntp < 2; ntp++) {
                        int row = nw * 32 + ntp * 16 + (lane & 7) + ((lane >> 4) << 3);
                        int ch  = ks * 2 + ((lane >> 3) & 1);
                        ldsm4(b[2*ntp][0], b[2*ntp][1], b[2*ntp+1][0], b[2*ntp+1][1],
                              wbase + row * 256 + ((ch ^ (row & 7)) << 4));
                    }
                    #pragma unroll
                    for (int mt = 0; mt < 2; mt++)
                        #pragma unroll
                        for (int nt = 0; nt < 4; nt++)
                            mma16816(acc[mt][nt], a[mt], b[nt]);
                }

                if (kc == 3) {
                    #pragma unroll
                    for (int mt = 0; mt < 2; mt++)
                        #pragma unroll
                        for (int nt = 0; nt < 4; nt++) {
                            int ng = nc * 128 + nw * 32 + nt * 8 + 2 * (lane & 3);
                            float2 bb = *(const float2*)(b2 + ng);
                            int r0 = m0 + mw * 32 + mt * 16 + (lane >> 2);
                            int r1 = r0 + 8;
                            if (r0 < M) {
                                __nv_bfloat162 o = __float22bfloat162_rn(
                                    make_float2(acc[mt][nt][0] + bb.x, acc[mt][nt][1] + bb.y));
                                *(unsigned*)(C + (size_t)r0 * D_SZ + ng) = *(unsigned*)&o;
                            }
                            if (r1 < M) {
                                __nv_bfloat162 o = __float22bfloat162_rn(
                                    make_float2(acc[mt][nt][2] + bb.x, acc[mt][nt][3] + bb.y));
                                *(unsigned*)(C + (size_t)r1 * D_SZ + ng) = *(unsigned*)&o;
                            }
                        }
                }
            }
        }
    }
}

// ---------------------------------------------------------------------------
// Prep: reset queue + 4x coalesced weight transpose (fp32 -> bf16 K-major)
// ---------------------------------------------------------------------------
__global__ __launch_bounds__(256) void prep_kernel(
    const float* __restrict__ cw1, const float* __restrict__ cw2,
    const float* __restrict__ tw1, const float* __restrict__ tw2)
{
    const int bx = blockIdx.x;
    const int tid = threadIdx.x;
    if (bx == 0 && tid == 0) g_tile = 0;      // reset queue each replay

    __shared__ float tile[32][33];
    const float* w; __nv_bfloat16* wt; int K, N, tt;
    if (bx < 64)       { w = cw1; wt = g_cw1t; K = S_SZ; N = H_SZ; tt = bx; }
    else if (bx < 128) { w = tw1; wt = g_tw1t; K = S_SZ; N = H_SZ; tt = bx - 64; }
    else if (bx < 256) { w = cw2; wt = g_cw2t; K = H_SZ; N = D_SZ; tt = bx - 128; }
    else               { w = tw2; wt = g_tw2t; K = H_SZ; N = D_SZ; tt = bx - 256; }

    const int Kt = K >> 5;
    const int kt = tt % Kt, nt = tt / Kt;
    const int cc = tid & 31, rr = tid >> 5;
    #pragma unroll
    for (int j = 0; j < 4; j++) {
        int row = rr + j * 8;
        tile[row][cc] = w[(size_t)(kt * 32 + row) * N + nt * 32 + cc];
    }
    __syncthreads();
    #pragma unroll
    for (int j = 0; j < 4; j++) {
        int row = rr + j * 8;
        wt[(size_t)(nt * 32 + row) * K + kt * 32 + cc] = __float2bfloat16(tile[cc][row]);
    }
}

// ---------------------------------------------------------------------------
// Scoring: one warp per pair, lane l owns cols [8l, 8l+8), bf16 g_v gathers,
// fully-unrolled K loop (wider load scheduling window). Fused final reduction.
// ---------------------------------------------------------------------------
__device__ __forceinline__ float clip10(float x) { return fminf(fmaxf(x, -10.f), 10.f); }
__device__ __forceinline__ float warp_reduce(float v) {
    #pragma unroll
    for (int s = 16; s > 0; s >>= 1) v += __shfl_xor_sync(0xffffffffu, v, s);
    return v;
}
__device__ __forceinline__ float dot8_bf16(const float* eu, uint4 q) {
    unsigned uu[4] = {q.x, q.y, q.z, q.w};
    float dn = 0.f;
    #pragma unroll
    for (int j = 0; j < 4; j++) {
        __nv_bfloat162 h = *(__nv_bfloat162*)&uu[j];
        float2 f = __bfloat1622float2(h);
        dn += eu[2*j+0] * f.x + eu[2*j+1] * f.y;
    }
    return dn;
}

__global__ __launch_bounds__(256) void score_kernel(
    const int* __restrict__ pos_u, const int* __restrict__ pos_v,
    const int* __restrict__ neg_v,
    const float* __restrict__ u_emb, float* __restrict__ out)
{
    __shared__ float bsum[8];
    __shared__ int lastflag;
    const int warp = threadIdx.x >> 5;
    const int lane = threadIdx.x & 31;
    const int b = blockIdx.x * 8 + warp;

    const int pu = pos_u[b];
    const int pv = pos_v[b];

    float eu[8];
    if (pu < NREG) {
        const float4* p = (const float4*)(u_emb + (size_t)pu * D_SZ);
        float4 f0 = p[lane * 2 + 0];
        float4 f1 = p[lane * 2 + 1];
        eu[0]=f0.x; eu[1]=f0.y; eu[2]=f0.z; eu[3]=f0.w;
        eu[4]=f1.x; eu[5]=f1.y; eu[6]=f1.z; eu[7]=f1.w;
    } else {
        uint4 q = ((const uint4*)(g_tu + (size_t)b * D_SZ))[lane];
        unsigned uu[4] = {q.x, q.y, q.z, q.w};
        #pragma unroll
        for (int j = 0; j < 4; j++) {
            __nv_bfloat162 h = *(__nv_bfloat162*)&uu[j];
            float2 f = __bfloat1622float2(h);
            eu[2*j+0] = f.x; eu[2*j+1] = f.y;
        }
    }

    uint4 qv = ((const uint4*)(g_v + (size_t)pv * D_SZ))[lane];
    float d = warp_reduce(dot8_bf16(eu, qv));
    float x = clip10(d);
    float s = __logf(1.f + __expf(-fabsf(x))) - fminf(x, 0.f);

    const int mynv = neg_v[(size_t)b * K_SZ + lane];
    #pragma unroll
    for (int k = 0; k < K_SZ; k++) {
        int nv = __shfl_sync(0xffffffffu, mynv, k);
        uint4 qn = ((const uint4*)(g_v + (size_t)nv * D_SZ))[lane];
        float dn = warp_reduce(dot8_bf16(eu, qn));
        float xn = clip10(dn);
        s += fmaxf(xn, 0.f) + __logf(1.f + __expf(-fabsf(xn)));
    }

    if (lane == 0) bsum[warp] = 2.f * s;
    __syncthreads();
    if (threadIdx.x == 0) {
        float t = 0.f;
        #pragma unroll
        for (int i = 0; i < 8; i++) t += bsum[i];
        g_partial[blockIdx.x] = t;
        __threadfence();
        unsigned old = atomicInc(&g_ticket, gridDim.x - 1);  // wraps -> replay-safe
        lastflag = (old == gridDim.x - 1);
    }
    __syncthreads();

    if (lastflag) {
        __threadfence();
        __shared__ float red[256];
        float v = 0.f;
        #pragma unroll
        for (int j = 0; j < 4; j++)
            v += __ldcg(&g_partial[threadIdx.x * 4 + j]);
        red[threadIdx.x] = v;
        __syncthreads();
        #pragma unroll
        for (int st = 128; st > 0; st >>= 1) {
            if (threadIdx.x < st) red[threadIdx.x] += red[threadIdx.x + st];
            __syncthreads();
        }
        if (threadIdx.x == 0) out[0] = red[0] / (float)B_SZ;
    }
}

// ---------------------------------------------------------------------------
// Launch
// ---------------------------------------------------------------------------
extern "C" void kernel_launch(void* const* d_in, const int* in_sizes, int n_in,
                              void* d_out, int out_size)
{
    const int*   pos_u  = (const int*)  d_in[0];
    const int*   pos_v  = (const int*)  d_in[1];
    const int*   neg_v  = (const int*)  d_in[2];
    const float* u_emb  = (const float*)d_in[3];
    const float* v_emb  = (const float*)d_in[4];
    const float* stoich = (const float*)d_in[5];
    const float* tw1    = (const float*)d_in[6];
    const float* tb1    = (const float*)d_in[7];
    const float* tw2    = (const float*)d_in[8];
    const float* tb2    = (const float*)d_in[9];
    const float* cw1    = (const float*)d_in[10];
    const float* cb1    = (const float*)d_in[11];
    const float* cw2    = (const float*)d_in[12];
    const float* cb2    = (const float*)d_in[13];
    float* out = (float*)d_out;

    static bool attr_set = false;
    if (!attr_set) {
        cudaFuncSetAttribute(work_kernel, cudaFuncAttributeMaxDynamicSharedMemorySize,
                             SM_TOTAL);
        attr_set = true;
    }

    // 1) reset queue + weight transposes
    prep_kernel<<<384, 256>>>(cw1, cw2, tw1, tw2);
    // 2) persistent work kernel (R13: 512 threads, serial per-tile prologue)
    work_kernel<<<GRID_W, NTHREADS, SM_TOTAL>>>(stoich, pos_u, v_emb, cb1, cb2, tb1, tb2);
    // 3) scoring (full K unroll) + fused final reduction
    score_kernel<<<B_SZ / 8, 256>>>(pos_u, pos_v, neg_v, u_emb, out);

    (void)in_sizes; (void)n_in; (void)out_size;
}